// round 12
// baseline (speedup 1.0000x reference)
#include <cuda_runtime.h>
#include <cuda_fp16.h>
#include <cstdint>
#include <cstddef>

#define EPSBN 1e-5f
#define N_B   8192
#define IN_F  512
#define H1D   1024
#define H2D   2048

// -------------------- scratch -----------------------------------------------
__device__ __align__(16) __half g_xs [2ULL * N_B * IN_F];
__device__ __align__(16) float  g_h1 [(size_t)N_B * 3 * H1D];
__device__ __align__(16) __half g_h1s[2ULL * 3 * N_B * H1D];
__device__ __align__(16) float  g_h2 [(size_t)3 * N_B * H2D];
__device__ __align__(16) __half g_h2s[2ULL * 3 * N_B * H2D];
__device__ __align__(16) float  g_h3 [(size_t)3 * N_B * H1D];
__device__ __align__(16) __half g_h3s[2ULL * 3 * N_B * H1D];
__device__ __align__(16) __half g_w1p[2ULL * 3 * H1D * IN_F];
__device__ __align__(16) __half g_w2p[2ULL * H2D * H1D];
__device__ __align__(16) __half g_w3p[2ULL * H1D * H2D];
__device__ __align__(16) __half g_w4p[2ULL * IN_F * H1D];
__device__ float g_c1[3 * H1D];
__device__ float g_c2[H2D];
__device__ float g_c3[H1D];
__device__ float g_c4[IN_F];

// -------------------- helpers ------------------------------------------------
__device__ __forceinline__ uint32_t smem_u32(const void* p) {
    uint32_t a;
    asm("{ .reg .u64 t; cvta.to.shared.u64 t, %1; cvt.u32.u64 %0, t; }" : "=r"(a) : "l"(p));
    return a;
}
__device__ __forceinline__ uint32_t h2u(__half2 h) { return *(uint32_t*)&h; }
__device__ __forceinline__ void split2x2(float x0, float x1, uint32_t& hi, uint32_t& lo) {
    __half2 h = __floats2half2_rn(x0, x1);
    float2 f = __half22float2(h);
    __half2 l = __floats2half2_rn(x0 - f.x, x1 - f.y);
    hi = h2u(h); lo = h2u(l);
}
__device__ __forceinline__ float bn_scale(float g, float v) {
    float vv = v + EPSBN;
    float a = rsqrtf(vv);
    return g * (a * (1.5f - 0.5f * vv * a * a));
}
__device__ __forceinline__ void lds_x4(uint32_t* r, uint32_t addr) {
    asm volatile("ldmatrix.sync.aligned.m8n8.x4.shared.b16 {%0,%1,%2,%3}, [%4];"
                 : "=r"(r[0]), "=r"(r[1]), "=r"(r[2]), "=r"(r[3]) : "r"(addr));
}
__device__ __forceinline__ void mma16816(float* c, const uint32_t* a, const uint32_t* b) {
    asm volatile(
        "mma.sync.aligned.m16n8k16.row.col.f32.f16.f16.f32 "
        "{%0,%1,%2,%3}, {%4,%5,%6,%7}, {%8,%9}, {%0,%1,%2,%3};"
        : "+f"(c[0]), "+f"(c[1]), "+f"(c[2]), "+f"(c[3])
        : "r"(a[0]), "r"(a[1]), "r"(a[2]), "r"(a[3]), "r"(b[0]), "r"(b[1]));
}
__device__ __forceinline__ void mma16816_z(float* c, const uint32_t* a, const uint32_t* b) {
    asm volatile(
        "mma.sync.aligned.m16n8k16.row.col.f32.f16.f16.f32 "
        "{%0,%1,%2,%3}, {%4,%5,%6,%7}, {%8,%9}, {%10,%10,%10,%10};"
        : "=f"(c[0]), "=f"(c[1]), "=f"(c[2]), "=f"(c[3])
        : "r"(a[0]), "r"(a[1]), "r"(a[2]), "r"(a[3]), "r"(b[0]), "r"(b[1]), "f"(0.f));
}

// -------------------- weight prep (vectorized by 2 along K) ------------------
__global__ void prep_w1_split(const float* __restrict__ W, const float* __restrict__ g,
                              const float* __restrict__ be, const float* __restrict__ m,
                              const float* __restrict__ v, __half* __restrict__ Wp,
                              float* __restrict__ bias) {
    int t = blockIdx.x * blockDim.x + threadIdx.x;
    if (t >= 3 * H1D * IN_F / 2) return;
    int i = 2 * t;
    int row = i >> 9;
    float a = bn_scale(g[row], v[row]);
    float2 w = *(const float2*)&W[i];
    const size_t S = (size_t)3 * H1D * IN_F;
    uint32_t hi, lo;
    split2x2(w.x * a, w.y * a, hi, lo);
    *(uint32_t*)&Wp[i] = hi;
    *(uint32_t*)&Wp[i + S] = lo;
    if ((i & (IN_F - 1)) == 0) bias[row] = be[row] - m[row] * a;
}

__global__ void prep_we_split(const float* __restrict__ W, const float* __restrict__ g,
                              const float* __restrict__ be, const float* __restrict__ m,
                              const float* __restrict__ v, __half* __restrict__ Wp,
                              float* __restrict__ bias, int Cout, int K) {
    int t = blockIdx.x * blockDim.x + threadIdx.x;
    if (t >= Cout * K / 2) return;
    int i = 2 * t;
    int o = i / K;
    int k = i - o * K;
    float ax = 0.f, ay = 0.f;
#pragma unroll
    for (int s = 0; s < 3; s++) {
        float a = bn_scale(g[s * Cout + o], v[s * Cout + o]);
        float2 w = *(const float2*)&W[(size_t)(s * Cout + o) * K + k];
        ax += a * w.x;
        ay += a * w.y;
    }
    const size_t S = (size_t)Cout * K;
    uint32_t hi, lo;
    split2x2(ax, ay, hi, lo);
    *(uint32_t*)&Wp[i] = hi;
    *(uint32_t*)&Wp[i + S] = lo;
    if (k == 0) {
        float cb = 0.f;
#pragma unroll
        for (int s = 0; s < 3; s++) {
            float a = bn_scale(g[s * Cout + o], v[s * Cout + o]);
            cb += be[s * Cout + o] - m[s * Cout + o] * a;
        }
        bias[o] = cb;
    }
}

// -------------------- activation split / gate --------------------------------
__global__ void split_x_kernel(const float* __restrict__ x, __half* __restrict__ o) {
    int i = blockIdx.x * blockDim.x + threadIdx.x;
    if (i >= N_B * IN_F / 4) return;
    float4 v = ((const float4*)x)[i];
    const size_t S = (size_t)N_B * IN_F;
    uint2 hi, lo;
    split2x2(v.x, v.y, hi.x, lo.x);
    split2x2(v.z, v.w, hi.y, lo.y);
    ((uint2*)o)[i] = hi;
    ((uint2*)(o + S))[i] = lo;
}

__global__ void gate1_split(const float* __restrict__ h1, __half* __restrict__ out) {
    int i = blockIdx.x * blockDim.x + threadIdx.x;
    if (i >= N_B * 128) return;
    int b = i >> 7;
    int o8 = i & 127;
    const float4* row = (const float4*)(h1 + (size_t)b * 3072);
    float4 va[3], vb[3];
#pragma unroll
    for (int s = 0; s < 3; s++) {
        va[s] = row[s * 256 + o8 * 2];
        vb[s] = row[s * 256 + o8 * 2 + 1];
    }
    float4 ma, mb;
    ma.x = (va[0].x + va[1].x + va[2].x > 0.f) ? 1.f : 0.f;
    ma.y = (va[0].y + va[1].y + va[2].y > 0.f) ? 1.f : 0.f;
    ma.z = (va[0].z + va[1].z + va[2].z > 0.f) ? 1.f : 0.f;
    ma.w = (va[0].w + va[1].w + va[2].w > 0.f) ? 1.f : 0.f;
    mb.x = (vb[0].x + vb[1].x + vb[2].x > 0.f) ? 1.f : 0.f;
    mb.y = (vb[0].y + vb[1].y + vb[2].y > 0.f) ? 1.f : 0.f;
    mb.z = (vb[0].z + vb[1].z + vb[2].z > 0.f) ? 1.f : 0.f;
    mb.w = (vb[0].w + vb[1].w + vb[2].w > 0.f) ? 1.f : 0.f;
    const size_t PL = (size_t)3 * N_B * H1D;
#pragma unroll
    for (int s = 0; s < 3; s++) {
        uint4 hi, lo;
        split2x2(va[s].x * ma.x, va[s].y * ma.y, hi.x, lo.x);
        split2x2(va[s].z * ma.z, va[s].w * ma.w, hi.y, lo.y);
        split2x2(vb[s].x * mb.x, vb[s].y * mb.y, hi.z, lo.z);
        split2x2(vb[s].z * mb.z, vb[s].w * mb.w, hi.w, lo.w);
        size_t base = (size_t)s * N_B * H1D + (size_t)b * H1D + (o8 << 3);
        *(uint4*)(out + base) = hi;
        *(uint4*)(out + PL + base) = lo;
    }
}

__global__ void gate_split(const float* __restrict__ h, __half* __restrict__ out,
                           size_t plane) {
    size_t i = (size_t)blockIdx.x * blockDim.x + threadIdx.x;
    size_t q8 = plane >> 3;
    if (i >= q8) return;
    const float4* h4 = (const float4*)h;
    size_t p4 = plane >> 2;
    size_t i2 = i * 2;
    float4 va[3], vb[3];
#pragma unroll
    for (int s = 0; s < 3; s++) {
        va[s] = h4[i2 + (size_t)s * p4];
        vb[s] = h4[i2 + 1 + (size_t)s * p4];
    }
    float4 ma, mb;
    ma.x = (va[0].x + va[1].x + va[2].x > 0.f) ? 1.f : 0.f;
    ma.y = (va[0].y + va[1].y + va[2].y > 0.f) ? 1.f : 0.f;
    ma.z = (va[0].z + va[1].z + va[2].z > 0.f) ? 1.f : 0.f;
    ma.w = (va[0].w + va[1].w + va[2].w > 0.f) ? 1.f : 0.f;
    mb.x = (vb[0].x + vb[1].x + vb[2].x > 0.f) ? 1.f : 0.f;
    mb.y = (vb[0].y + vb[1].y + vb[2].y > 0.f) ? 1.f : 0.f;
    mb.z = (vb[0].z + vb[1].z + vb[2].z > 0.f) ? 1.f : 0.f;
    mb.w = (vb[0].w + vb[1].w + vb[2].w > 0.f) ? 1.f : 0.f;
    const size_t PL = 3 * plane;
#pragma unroll
    for (int s = 0; s < 3; s++) {
        uint4 hi, lo;
        split2x2(va[s].x * ma.x, va[s].y * ma.y, hi.x, lo.x);
        split2x2(va[s].z * ma.z, va[s].w * ma.w, hi.y, lo.y);
        split2x2(vb[s].x * mb.x, vb[s].y * mb.y, hi.z, lo.z);
        split2x2(vb[s].z * mb.z, vb[s].w * mb.w, hi.w, lo.w);
        size_t base = (size_t)s * plane + (i << 3);
        *(uint4*)(out + base) = hi;
        *(uint4*)(out + PL + base) = lo;
    }
}

// -------------------- fused 3-product fp16 HMMA GEMM, 128x256 tile -----------
// C = hh + hl + lh + bias. CTA 128x256, 8 warps (2x4), warp tile 64x64 in two
// 64x32-wide n-halves... (warp grid 2m x 4n, each warp 64 rows x 64 cols,
// processed as two 64x32 halves? no: two n-halves of 32 cols each per warp).
// Stage = K64: A 2x16KB + B 2x32KB = 96KB, double-buffered (192KB).
// tacc chain = 12 mma per 64-K chunk (validated), RN drain per chunk.
#define ATSZ 16384
#define BTSZ 32768
#define STAGE (2 * ATSZ + 2 * BTSZ)
#define SMEM_BYTES (2 * STAGE)

__device__ __forceinline__ void load_rows16(uint32_t dst, const __half* src, int row0,
                                            int nrows, int KD, int k0, int tid) {
    int total = nrows * 8;
    for (int id = tid; id < total; id += 256) {
        int row = id >> 3, c = id & 7;
        uint32_t d = dst + (row << 7) + (((c ^ row) & 7) << 4);
        const void* s = (const char*)(src + (size_t)(row0 + row) * KD + k0) + (c << 4);
        asm volatile("cp.async.cg.shared.global [%0], [%1], 16;" :: "r"(d), "l"(s));
    }
}

__device__ __forceinline__ void load_super(uint32_t buf, const __half* A0,
                                           const __half* B0, size_t pas, size_t pbs,
                                           int m0, int n0, int KD, int k0, int tid) {
#pragma unroll
    for (int lvl = 0; lvl < 2; lvl++) {
        load_rows16(buf + lvl * ATSZ, A0 + (size_t)lvl * pas, m0, 128, KD, k0, tid);
        load_rows16(buf + 2 * ATSZ + lvl * BTSZ, B0 + (size_t)lvl * pbs, n0, 256, KD, k0, tid);
    }
    asm volatile("cp.async.commit_group;" ::: "memory");
}

template <int KDIM, int ILV>
__global__ void __launch_bounds__(256, 1)
gemm_fused(const __half* __restrict__ A0, const __half* __restrict__ B0,
           const float* __restrict__ bias, float* __restrict__ C, int M, int N) {
    extern __shared__ __align__(1024) char dsm[];
    const uint32_t Sb = smem_u32(dsm);

    const int tid = threadIdx.x;
    const int wid = tid >> 5;
    const int lane = tid & 31;
    const int warp_m = wid & 1;       // 2 warps in M
    const int warp_n = wid >> 1;      // 4 warps in N (64 cols each)
    const int m0 = blockIdx.y * 128;
    const int n0 = blockIdx.x * 256;

    uint32_t aoff[4];
#pragma unroll
    for (int mt = 0; mt < 4; mt++)
        aoff[mt] = (uint32_t)(warp_m * 64 + mt * 16 + (lane & 15)) << 7;
    const int brow_sel = ((lane >> 4) << 3) + (lane & 7);
    const int l7 = lane & 7;
    const int cha = lane >> 4;
    const int chb = (lane >> 3) & 1;

    float acc[4][8][4];
#pragma unroll
    for (int i = 0; i < 4; i++)
#pragma unroll
        for (int j = 0; j < 8; j++)
#pragma unroll
            for (int q = 0; q < 4; q++) acc[i][j][q] = 0.f;

    constexpr int NSUP = KDIM / 64;
    const size_t pas = (size_t)M * KDIM, pbs = (size_t)N * KDIM;

    load_super(Sb, A0, B0, pas, pbs, m0, n0, KDIM, 0, tid);

    for (int t = 0; t < NSUP; t++) {
        asm volatile("cp.async.wait_group 0;" ::: "memory");
        __syncthreads();

        if (t + 1 < NSUP)
            load_super(Sb + ((t + 1) & 1) * STAGE, A0, B0, pas, pbs, m0, n0, KDIM,
                       (t + 1) * 64, tid);

        const uint32_t Ab = Sb + (t & 1) * STAGE;
        const uint32_t Bb = Ab + 2 * ATSZ;

#pragma unroll
        for (int nh = 0; nh < 2; nh++) {
            float tacc[4][4][4];   // zero-written by first mma
#pragma unroll
            for (int kk = 0; kk < 4; kk++) {
                const uint32_t swa = (uint32_t)(((2 * kk + cha) ^ l7) & 7) << 4;
                const uint32_t swb = (uint32_t)(((2 * kk + chb) ^ l7) & 7) << 4;

                uint32_t b[2][2][4];
#pragma unroll
                for (int lvl = 0; lvl < 2; lvl++)
#pragma unroll
                    for (int np = 0; np < 2; np++) {
                        uint32_t boff =
                            (uint32_t)(warp_n * 64 + nh * 32 + np * 16 + brow_sel) << 7;
                        lds_x4(b[lvl][np], Bb + lvl * BTSZ + boff + swb);
                    }

                uint32_t a[4][4];
                // ---- A hi: hh, hl ----
#pragma unroll
                for (int mt = 0; mt < 4; mt++) lds_x4(a[mt], Ab + aoff[mt] + swa);
                if (kk == 0) {
#pragma unroll
                    for (int mt = 0; mt < 4; mt++)
#pragma unroll
                        for (int nt = 0; nt < 4; nt++)
                            mma16816_z(tacc[mt][nt], a[mt], &b[0][nt >> 1][(nt & 1) * 2]);
                } else {
#pragma unroll
                    for (int mt = 0; mt < 4; mt++)
#pragma unroll
                        for (int nt = 0; nt < 4; nt++)
                            mma16816(tacc[mt][nt], a[mt], &b[0][nt >> 1][(nt & 1) * 2]);
                }
#pragma unroll
                for (int mt = 0; mt < 4; mt++)
#pragma unroll
                    for (int nt = 0; nt < 4; nt++)
                        mma16816(tacc[mt][nt], a[mt], &b[1][nt >> 1][(nt & 1) * 2]);
                // ---- A lo: lh ----
#pragma unroll
                for (int mt = 0; mt < 4; mt++) lds_x4(a[mt], Ab + ATSZ + aoff[mt] + swa);
#pragma unroll
                for (int mt = 0; mt < 4; mt++)
#pragma unroll
                    for (int nt = 0; nt < 4; nt++)
                        mma16816(tacc[mt][nt], a[mt], &b[0][nt >> 1][(nt & 1) * 2]);
            }
            // RN drain (chain 12)
#pragma unroll
            for (int i = 0; i < 4; i++)
#pragma unroll
                for (int j = 0; j < 4; j++)
#pragma unroll
                    for (int q = 0; q < 4; q++) acc[i][nh * 4 + j][q] += tacc[i][j][q];
        }
    }

    // -------------------- epilogue --------------------
#pragma unroll
    for (int mt = 0; mt < 4; mt++) {
#pragma unroll
        for (int nt = 0; nt < 8; nt++) {
            int r0 = m0 + warp_m * 64 + mt * 16 + (lane >> 2);
            int cc = n0 + warp_n * 64 + nt * 8 + (lane & 3) * 2;
            float b0 = bias[cc], b1 = bias[cc + 1];
            float* ac = acc[mt][nt];
            if (!ILV) {
                float2 v0 = make_float2(ac[0] + b0, ac[1] + b1);
                float2 v1 = make_float2(ac[2] + b0, ac[3] + b1);
                *(float2*)(C + (size_t)r0 * N + cc) = v0;
                *(float2*)(C + (size_t)(r0 + 8) * N + cc) = v1;
            } else {
                int s0 = r0 >> 13, bb0 = r0 & 8191;
                int r1 = r0 + 8;
                int s1 = r1 >> 13, bb1 = r1 & 8191;
                C[(size_t)bb0 * (N * 3) + (size_t)cc * 3 + s0] = ac[0] + b0;
                C[(size_t)bb0 * (N * 3) + (size_t)(cc + 1) * 3 + s0] = ac[1] + b1;
                C[(size_t)bb1 * (N * 3) + (size_t)cc * 3 + s1] = ac[2] + b0;
                C[(size_t)bb1 * (N * 3) + (size_t)(cc + 1) * 3 + s1] = ac[3] + b1;
            }
        }
    }
}

// -------------------- launch --------------------------------------------------
extern "C" void kernel_launch(void* const* d_in, const int* in_sizes, int n_in,
                              void* d_out, int out_size) {
    const float* x  = (const float*)d_in[0];
    const float *W1 = (const float*)d_in[1],  *G1 = (const float*)d_in[2],
                *B1 = (const float*)d_in[3],  *M1 = (const float*)d_in[4],
                *V1 = (const float*)d_in[5];
    const float *W2 = (const float*)d_in[6],  *G2 = (const float*)d_in[7],
                *B2 = (const float*)d_in[8],  *M2 = (const float*)d_in[9],
                *V2 = (const float*)d_in[10];
    const float *W3 = (const float*)d_in[11], *G3 = (const float*)d_in[12],
                *B3 = (const float*)d_in[13], *M3 = (const float*)d_in[14],
                *V3 = (const float*)d_in[15];
    const float *W4 = (const float*)d_in[16], *G4 = (const float*)d_in[17],
                *B4 = (const float*)d_in[18], *M4 = (const float*)d_in[19],
                *V4 = (const float*)d_in[20];
    float* out = (float*)d_out;

    __half *xs, *h1s, *h2s, *h3s, *w1p, *w2p, *w3p, *w4p;
    float *h1, *h2, *h3, *c1, *c2, *c3, *c4;
    cudaGetSymbolAddress((void**)&xs, g_xs);
    cudaGetSymbolAddress((void**)&h1, g_h1);
    cudaGetSymbolAddress((void**)&h1s, g_h1s);
    cudaGetSymbolAddress((void**)&h2, g_h2);
    cudaGetSymbolAddress((void**)&h2s, g_h2s);
    cudaGetSymbolAddress((void**)&h3, g_h3);
    cudaGetSymbolAddress((void**)&h3s, g_h3s);
    cudaGetSymbolAddress((void**)&w1p, g_w1p);
    cudaGetSymbolAddress((void**)&w2p, g_w2p);
    cudaGetSymbolAddress((void**)&w3p, g_w3p);
    cudaGetSymbolAddress((void**)&w4p, g_w4p);
    cudaGetSymbolAddress((void**)&c1, g_c1);
    cudaGetSymbolAddress((void**)&c2, g_c2);
    cudaGetSymbolAddress((void**)&c3, g_c3);
    cudaGetSymbolAddress((void**)&c4, g_c4);

    cudaFuncSetAttribute(gemm_fused<512, 0>,  cudaFuncAttributeMaxDynamicSharedMemorySize, SMEM_BYTES);
    cudaFuncSetAttribute(gemm_fused<1024, 0>, cudaFuncAttributeMaxDynamicSharedMemorySize, SMEM_BYTES);
    cudaFuncSetAttribute(gemm_fused<2048, 0>, cudaFuncAttributeMaxDynamicSharedMemorySize, SMEM_BYTES);
    cudaFuncSetAttribute(gemm_fused<1024, 1>, cudaFuncAttributeMaxDynamicSharedMemorySize, SMEM_BYTES);

    const int T = 256;
    split_x_kernel<<<(N_B * IN_F / 4 + T - 1) / T, T>>>(x, xs);
    prep_w1_split<<<(3 * H1D * IN_F / 2 + T - 1) / T, T>>>(W1, G1, B1, M1, V1, w1p, c1);
    prep_we_split<<<(H2D * H1D / 2 + T - 1) / T, T>>>(W2, G2, B2, M2, V2, w2p, c2, H2D, H1D);
    prep_we_split<<<(H1D * H2D / 2 + T - 1) / T, T>>>(W3, G3, B3, M3, V3, w3p, c3, H1D, H2D);
    prep_we_split<<<(IN_F * H1D / 2 + T - 1) / T, T>>>(W4, G4, B4, M4, V4, w4p, c4, IN_F, H1D);

    // L1: [8192,512] x [3072,512]^T -> h1 [8192,3072]
    gemm_fused<512, 0><<<dim3(3 * H1D / 256, N_B / 128), T, SMEM_BYTES>>>(xs, w1p, c1, h1, N_B, 3 * H1D);
    gate1_split<<<(N_B * 128 + T - 1) / T, T>>>(h1, h1s);
    // L2: [24576,1024] x [2048,1024]^T
    gemm_fused<1024, 0><<<dim3(H2D / 256, 3 * N_B / 128), T, SMEM_BYTES>>>(h1s, w2p, c2, h2, 3 * N_B, H2D);
    gate_split<<<(int)((N_B * (size_t)H2D / 8 + T - 1) / T), T>>>(h2, h2s, (size_t)N_B * H2D);
    // L3: [24576,2048] x [1024,2048]^T
    gemm_fused<2048, 0><<<dim3(H1D / 256, 3 * N_B / 128), T, SMEM_BYTES>>>(h2s, w3p, c3, h3, 3 * N_B, H1D);
    gate_split<<<(int)((N_B * (size_t)H1D / 8 + T - 1) / T), T>>>(h3, h3s, (size_t)N_B * H1D);
    // L4: [24576,1024] x [512,1024]^T -> interleaved out [b][o][s]
    gemm_fused<1024, 1><<<dim3(IN_F / 256, 3 * N_B / 128), T, SMEM_BYTES>>>(h3s, w4p, c4, out, 3 * N_B, IN_F);
}

// round 13
// speedup vs baseline: 1.3599x; 1.3599x over previous
#include <cuda_runtime.h>
#include <cuda_fp16.h>
#include <cstdint>
#include <cstddef>

#define EPSBN 1e-5f
#define N_B   8192
#define IN_F  512
#define H1D   1024
#define H2D   2048

// -------------------- scratch -----------------------------------------------
__device__ __align__(16) __half g_xs [2ULL * N_B * IN_F];
__device__ __align__(16) float  g_h1 [(size_t)N_B * 3 * H1D];
__device__ __align__(16) __half g_h1s[2ULL * 3 * N_B * H1D];
__device__ __align__(16) float  g_h2 [(size_t)3 * N_B * H2D];
__device__ __align__(16) __half g_h2s[2ULL * 3 * N_B * H2D];
__device__ __align__(16) float  g_h3 [(size_t)3 * N_B * H1D];
__device__ __align__(16) __half g_h3s[2ULL * 3 * N_B * H1D];
__device__ __align__(16) __half g_w1p[2ULL * 3 * H1D * IN_F];
__device__ __align__(16) __half g_w2p[2ULL * H2D * H1D];
__device__ __align__(16) __half g_w3p[2ULL * H1D * H2D];
__device__ __align__(16) __half g_w4p[2ULL * IN_F * H1D];
__device__ float g_c1[3 * H1D];
__device__ float g_c2[H2D];
__device__ float g_c3[H1D];
__device__ float g_c4[IN_F];

// -------------------- helpers ------------------------------------------------
__device__ __forceinline__ uint32_t smem_u32(const void* p) {
    uint32_t a;
    asm("{ .reg .u64 t; cvta.to.shared.u64 t, %1; cvt.u32.u64 %0, t; }" : "=r"(a) : "l"(p));
    return a;
}
__device__ __forceinline__ uint32_t h2u(__half2 h) { return *(uint32_t*)&h; }
__device__ __forceinline__ void split2x2(float x0, float x1, uint32_t& hi, uint32_t& lo) {
    __half2 h = __floats2half2_rn(x0, x1);
    float2 f = __half22float2(h);
    __half2 l = __floats2half2_rn(x0 - f.x, x1 - f.y);
    hi = h2u(h); lo = h2u(l);
}
__device__ __forceinline__ float bn_scale(float g, float v) {
    float vv = v + EPSBN;
    float a = rsqrtf(vv);
    return g * (a * (1.5f - 0.5f * vv * a * a));
}
__device__ __forceinline__ void lds_x4(uint32_t* r, uint32_t addr) {
    asm volatile("ldmatrix.sync.aligned.m8n8.x4.shared.b16 {%0,%1,%2,%3}, [%4];"
                 : "=r"(r[0]), "=r"(r[1]), "=r"(r[2]), "=r"(r[3]) : "r"(addr));
}
__device__ __forceinline__ void mma16816(float* c, const uint32_t* a, const uint32_t* b) {
    asm volatile(
        "mma.sync.aligned.m16n8k16.row.col.f32.f16.f16.f32 "
        "{%0,%1,%2,%3}, {%4,%5,%6,%7}, {%8,%9}, {%0,%1,%2,%3};"
        : "+f"(c[0]), "+f"(c[1]), "+f"(c[2]), "+f"(c[3])
        : "r"(a[0]), "r"(a[1]), "r"(a[2]), "r"(a[3]), "r"(b[0]), "r"(b[1]));
}
__device__ __forceinline__ void mma16816_z(float* c, const uint32_t* a, const uint32_t* b) {
    asm volatile(
        "mma.sync.aligned.m16n8k16.row.col.f32.f16.f16.f32 "
        "{%0,%1,%2,%3}, {%4,%5,%6,%7}, {%8,%9}, {%10,%10,%10,%10};"
        : "=f"(c[0]), "=f"(c[1]), "=f"(c[2]), "=f"(c[3])
        : "r"(a[0]), "r"(a[1]), "r"(a[2]), "r"(a[3]), "r"(b[0]), "r"(b[1]), "f"(0.f));
}

// -------------------- weight prep (vectorized by 2 along K) ------------------
__global__ void prep_w1_split(const float* __restrict__ W, const float* __restrict__ g,
                              const float* __restrict__ be, const float* __restrict__ m,
                              const float* __restrict__ v, __half* __restrict__ Wp,
                              float* __restrict__ bias) {
    int t = blockIdx.x * blockDim.x + threadIdx.x;
    if (t >= 3 * H1D * IN_F / 2) return;
    int i = 2 * t;
    int row = i >> 9;
    float a = bn_scale(g[row], v[row]);
    float2 w = *(const float2*)&W[i];
    const size_t S = (size_t)3 * H1D * IN_F;
    uint32_t hi, lo;
    split2x2(w.x * a, w.y * a, hi, lo);
    *(uint32_t*)&Wp[i] = hi;
    *(uint32_t*)&Wp[i + S] = lo;
    if ((i & (IN_F - 1)) == 0) bias[row] = be[row] - m[row] * a;
}

__global__ void prep_we_split(const float* __restrict__ W, const float* __restrict__ g,
                              const float* __restrict__ be, const float* __restrict__ m,
                              const float* __restrict__ v, __half* __restrict__ Wp,
                              float* __restrict__ bias, int Cout, int K) {
    int t = blockIdx.x * blockDim.x + threadIdx.x;
    if (t >= Cout * K / 2) return;
    int i = 2 * t;
    int o = i / K;
    int k = i - o * K;
    float ax = 0.f, ay = 0.f;
#pragma unroll
    for (int s = 0; s < 3; s++) {
        float a = bn_scale(g[s * Cout + o], v[s * Cout + o]);
        float2 w = *(const float2*)&W[(size_t)(s * Cout + o) * K + k];
        ax += a * w.x;
        ay += a * w.y;
    }
    const size_t S = (size_t)Cout * K;
    uint32_t hi, lo;
    split2x2(ax, ay, hi, lo);
    *(uint32_t*)&Wp[i] = hi;
    *(uint32_t*)&Wp[i + S] = lo;
    if (k == 0) {
        float cb = 0.f;
#pragma unroll
        for (int s = 0; s < 3; s++) {
            float a = bn_scale(g[s * Cout + o], v[s * Cout + o]);
            cb += be[s * Cout + o] - m[s * Cout + o] * a;
        }
        bias[o] = cb;
    }
}

// -------------------- activation split / gate --------------------------------
__global__ void split_x_kernel(const float* __restrict__ x, __half* __restrict__ o) {
    int i = blockIdx.x * blockDim.x + threadIdx.x;
    if (i >= N_B * IN_F / 4) return;
    float4 v = ((const float4*)x)[i];
    const size_t S = (size_t)N_B * IN_F;
    uint2 hi, lo;
    split2x2(v.x, v.y, hi.x, lo.x);
    split2x2(v.z, v.w, hi.y, lo.y);
    ((uint2*)o)[i] = hi;
    ((uint2*)(o + S))[i] = lo;
}

// gate core: 4 fp32 -> mask -> gated hi/lo (identical math/order to R10)
__device__ __forceinline__ void gate_pack4(const float4 v[3], uint4* hi4, uint4* lo4,
                                           int part) {
    float4 mk;
    mk.x = (v[0].x + v[1].x + v[2].x > 0.f) ? 1.f : 0.f;
    mk.y = (v[0].y + v[1].y + v[2].y > 0.f) ? 1.f : 0.f;
    mk.z = (v[0].z + v[1].z + v[2].z > 0.f) ? 1.f : 0.f;
    mk.w = (v[0].w + v[1].w + v[2].w > 0.f) ? 1.f : 0.f;
#pragma unroll
    for (int s = 0; s < 3; s++) {
        uint32_t h0, l0, h1, l1;
        split2x2(v[s].x * mk.x, v[s].y * mk.y, h0, l0);
        split2x2(v[s].z * mk.z, v[s].w * mk.w, h1, l1);
        uint32_t* hp = (uint32_t*)&hi4[s];
        uint32_t* lp = (uint32_t*)&lo4[s];
        hp[part * 2] = h0; hp[part * 2 + 1] = h1;
        lp[part * 2] = l0; lp[part * 2 + 1] = l1;
    }
}

// h1 fp32 [b][s*1024+o] -> gated+split [lvl][s][b][o]; 16 elems/plane/thread
__global__ void gate1_split(const float* __restrict__ h1, __half* __restrict__ out) {
    int i = blockIdx.x * blockDim.x + threadIdx.x;
    if (i >= N_B * 64) return;
    int b = i >> 6;
    int o16 = i & 63;
    const float4* row = (const float4*)(h1 + (size_t)b * 3072);
    const size_t PL = (size_t)3 * N_B * H1D;
    size_t base0 = (size_t)b * H1D + (o16 << 4);
#pragma unroll
    for (int g = 0; g < 2; g++) {   // two 8-elem groups
        float4 va[3], vb[3];
#pragma unroll
        for (int s = 0; s < 3; s++) {
            va[s] = row[s * 256 + o16 * 4 + g * 2];
            vb[s] = row[s * 256 + o16 * 4 + g * 2 + 1];
        }
        uint4 hi[3], lo[3];
        gate_pack4(va, hi, lo, 0);
        gate_pack4(vb, hi, lo, 1);
#pragma unroll
        for (int s = 0; s < 3; s++) {
            size_t base = (size_t)s * N_B * H1D + base0 + g * 8;
            *(uint4*)(out + base) = hi[s];
            *(uint4*)(out + PL + base) = lo[s];
        }
    }
}

// h fp32 plane-major [s][plane] -> gated+split [lvl][s][plane]; 16 elems/thread
__global__ void gate_split(const float* __restrict__ h, __half* __restrict__ out,
                           size_t plane) {
    size_t i = (size_t)blockIdx.x * blockDim.x + threadIdx.x;
    size_t q16 = plane >> 4;
    if (i >= q16) return;
    const float4* h4 = (const float4*)h;
    size_t p4 = plane >> 2;
    size_t i4 = i * 4;
    const size_t PL = 3 * plane;
#pragma unroll
    for (int g = 0; g < 2; g++) {
        float4 va[3], vb[3];
#pragma unroll
        for (int s = 0; s < 3; s++) {
            va[s] = h4[i4 + g * 2 + (size_t)s * p4];
            vb[s] = h4[i4 + g * 2 + 1 + (size_t)s * p4];
        }
        uint4 hi[3], lo[3];
        gate_pack4(va, hi, lo, 0);
        gate_pack4(vb, hi, lo, 1);
#pragma unroll
        for (int s = 0; s < 3; s++) {
            size_t base = (size_t)s * plane + (i << 4) + g * 8;
            *(uint4*)(out + base) = hi[s];
            *(uint4*)(out + PL + base) = lo[s];
        }
    }
}

// -------------------- fused 3-product fp16 HMMA GEMM (R10 config) ------------
// C = hh + hl + lh + bias. 128x128 tile, triple-buffered 64KB super-stages
// (192KB smem), cp.async 2 ahead, wait_group 1. tacc chain = 12 mma,
// RN drain per stage.
#define TSZ 16384
#define SUPER (4 * TSZ)
#define NBUF 3
#define SMEM_BYTES (NBUF * SUPER)

__device__ __forceinline__ void load_tile16(uint32_t dst, const __half* src,
                                            int row0, int KD, int k0, int tid) {
#pragma unroll
    for (int j = 0; j < 4; j++) {
        int id = j * 256 + tid;
        int row = id >> 3, c = id & 7;
        uint32_t d = dst + (row << 7) + (((c ^ row) & 7) << 4);
        const void* s = (const char*)(src + (size_t)(row0 + row) * KD + k0) + (c << 4);
        asm volatile("cp.async.cg.shared.global [%0], [%1], 16;" :: "r"(d), "l"(s));
    }
}

__device__ __forceinline__ void load_super(uint32_t buf, const __half* A0,
                                           const __half* B0, size_t pas, size_t pbs,
                                           int m0, int n0, int KD, int k0, int tid) {
#pragma unroll
    for (int lvl = 0; lvl < 2; lvl++) {
        load_tile16(buf + lvl * TSZ, A0 + (size_t)lvl * pas, m0, KD, k0, tid);
        load_tile16(buf + (2 + lvl) * TSZ, B0 + (size_t)lvl * pbs, n0, KD, k0, tid);
    }
    asm volatile("cp.async.commit_group;" ::: "memory");
}

template <int KDIM, int ILV>
__global__ void __launch_bounds__(256, 1)
gemm_fused(const __half* __restrict__ A0, const __half* __restrict__ B0,
           const float* __restrict__ bias, float* __restrict__ C, int M, int N) {
    extern __shared__ __align__(1024) char dsm[];
    const uint32_t Sb = smem_u32(dsm);

    const int tid = threadIdx.x;
    const int wid = tid >> 5;
    const int lane = tid & 31;
    const int warp_m = wid & 1;
    const int warp_n = wid >> 1;
    const int m0 = blockIdx.y * 128;
    const int n0 = blockIdx.x * 128;

    uint32_t aoff[4], boff[2];
#pragma unroll
    for (int mt = 0; mt < 4; mt++)
        aoff[mt] = (uint32_t)(warp_m * 64 + mt * 16 + (lane & 15)) << 7;
#pragma unroll
    for (int np = 0; np < 2; np++)
        boff[np] = (uint32_t)(warp_n * 32 + np * 16 + ((lane >> 4) << 3) + (lane & 7)) << 7;
    const int l7 = lane & 7;
    const int cha = lane >> 4;
    const int chb = (lane >> 3) & 1;

    float acc[4][4][4];
#pragma unroll
    for (int i = 0; i < 4; i++)
#pragma unroll
        for (int j = 0; j < 4; j++)
#pragma unroll
            for (int q = 0; q < 4; q++) acc[i][j][q] = 0.f;

    constexpr int NSUP = KDIM / 64;
    const size_t pas = (size_t)M * KDIM, pbs = (size_t)N * KDIM;

    load_super(Sb + 0 * SUPER, A0, B0, pas, pbs, m0, n0, KDIM, 0, tid);
    load_super(Sb + 1 * SUPER, A0, B0, pas, pbs, m0, n0, KDIM, 64, tid);

    int buf_c = 0;
    for (int t = 0; t < NSUP; t++) {
        if (t + 1 < NSUP) {
            asm volatile("cp.async.wait_group 1;" ::: "memory");
        } else {
            asm volatile("cp.async.wait_group 0;" ::: "memory");
        }
        __syncthreads();

        if (t + 2 < NSUP) {
            int buf_n = buf_c + 2;
            if (buf_n >= NBUF) buf_n -= NBUF;
            load_super(Sb + buf_n * SUPER, A0, B0, pas, pbs, m0, n0, KDIM,
                       (t + 2) * 64, tid);
        }

        const uint32_t Ab = Sb + buf_c * SUPER;
        const uint32_t Bb = Ab + 2 * TSZ;

        float tacc[4][4][4];
#pragma unroll
        for (int kk = 0; kk < 4; kk++) {
            const uint32_t swa = (uint32_t)(((2 * kk + cha) ^ l7) & 7) << 4;
            const uint32_t swb = (uint32_t)(((2 * kk + chb) ^ l7) & 7) << 4;

            uint32_t b[2][2][4];
#pragma unroll
            for (int lvl = 0; lvl < 2; lvl++)
#pragma unroll
                for (int np = 0; np < 2; np++)
                    lds_x4(b[lvl][np], Bb + lvl * TSZ + boff[np] + swb);

            uint32_t a[4][4];
#pragma unroll
            for (int mt = 0; mt < 4; mt++) lds_x4(a[mt], Ab + 0 * TSZ + aoff[mt] + swa);
            if (kk == 0) {
#pragma unroll
                for (int mt = 0; mt < 4; mt++)
#pragma unroll
                    for (int nt = 0; nt < 4; nt++)
                        mma16816_z(tacc[mt][nt], a[mt], &b[0][nt >> 1][(nt & 1) * 2]);
            } else {
#pragma unroll
                for (int mt = 0; mt < 4; mt++)
#pragma unroll
                    for (int nt = 0; nt < 4; nt++)
                        mma16816(tacc[mt][nt], a[mt], &b[0][nt >> 1][(nt & 1) * 2]);
            }
#pragma unroll
            for (int mt = 0; mt < 4; mt++)
#pragma unroll
                for (int nt = 0; nt < 4; nt++)
                    mma16816(tacc[mt][nt], a[mt], &b[1][nt >> 1][(nt & 1) * 2]);
#pragma unroll
            for (int mt = 0; mt < 4; mt++) lds_x4(a[mt], Ab + 1 * TSZ + aoff[mt] + swa);
#pragma unroll
            for (int mt = 0; mt < 4; mt++)
#pragma unroll
                for (int nt = 0; nt < 4; nt++)
                    mma16816(tacc[mt][nt], a[mt], &b[0][nt >> 1][(nt & 1) * 2]);
        }
#pragma unroll
        for (int i = 0; i < 4; i++)
#pragma unroll
            for (int j = 0; j < 4; j++)
#pragma unroll
                for (int q = 0; q < 4; q++) acc[i][j][q] += tacc[i][j][q];

        buf_c++;
        if (buf_c >= NBUF) buf_c -= NBUF;
    }

    // -------------------- epilogue --------------------
#pragma unroll
    for (int mt = 0; mt < 4; mt++) {
#pragma unroll
        for (int nt = 0; nt < 4; nt++) {
            int r0 = m0 + warp_m * 64 + mt * 16 + (lane >> 2);
            int cc = n0 + warp_n * 32 + nt * 8 + (lane & 3) * 2;
            float b0 = bias[cc], b1 = bias[cc + 1];
            float* ac = acc[mt][nt];
            if (!ILV) {
                float2 v0 = make_float2(ac[0] + b0, ac[1] + b1);
                float2 v1 = make_float2(ac[2] + b0, ac[3] + b1);
                *(float2*)(C + (size_t)r0 * N + cc) = v0;
                *(float2*)(C + (size_t)(r0 + 8) * N + cc) = v1;
            } else {
                int s0 = r0 >> 13, bb0 = r0 & 8191;
                int r1 = r0 + 8;
                int s1 = r1 >> 13, bb1 = r1 & 8191;
                C[(size_t)bb0 * (N * 3) + (size_t)cc * 3 + s0] = ac[0] + b0;
                C[(size_t)bb0 * (N * 3) + (size_t)(cc + 1) * 3 + s0] = ac[1] + b1;
                C[(size_t)bb1 * (N * 3) + (size_t)cc * 3 + s1] = ac[2] + b0;
                C[(size_t)bb1 * (N * 3) + (size_t)(cc + 1) * 3 + s1] = ac[3] + b1;
            }
        }
    }
}

// -------------------- launch --------------------------------------------------
extern "C" void kernel_launch(void* const* d_in, const int* in_sizes, int n_in,
                              void* d_out, int out_size) {
    const float* x  = (const float*)d_in[0];
    const float *W1 = (const float*)d_in[1],  *G1 = (const float*)d_in[2],
                *B1 = (const float*)d_in[3],  *M1 = (const float*)d_in[4],
                *V1 = (const float*)d_in[5];
    const float *W2 = (const float*)d_in[6],  *G2 = (const float*)d_in[7],
                *B2 = (const float*)d_in[8],  *M2 = (const float*)d_in[9],
                *V2 = (const float*)d_in[10];
    const float *W3 = (const float*)d_in[11], *G3 = (const float*)d_in[12],
                *B3 = (const float*)d_in[13], *M3 = (const float*)d_in[14],
                *V3 = (const float*)d_in[15];
    const float *W4 = (const float*)d_in[16], *G4 = (const float*)d_in[17],
                *B4 = (const float*)d_in[18], *M4 = (const float*)d_in[19],
                *V4 = (const float*)d_in[20];
    float* out = (float*)d_out;

    __half *xs, *h1s, *h2s, *h3s, *w1p, *w2p, *w3p, *w4p;
    float *h1, *h2, *h3, *c1, *c2, *c3, *c4;
    cudaGetSymbolAddress((void**)&xs, g_xs);
    cudaGetSymbolAddress((void**)&h1, g_h1);
    cudaGetSymbolAddress((void**)&h1s, g_h1s);
    cudaGetSymbolAddress((void**)&h2, g_h2);
    cudaGetSymbolAddress((void**)&h2s, g_h2s);
    cudaGetSymbolAddress((void**)&h3, g_h3);
    cudaGetSymbolAddress((void**)&h3s, g_h3s);
    cudaGetSymbolAddress((void**)&w1p, g_w1p);
    cudaGetSymbolAddress((void**)&w2p, g_w2p);
    cudaGetSymbolAddress((void**)&w3p, g_w3p);
    cudaGetSymbolAddress((void**)&w4p, g_w4p);
    cudaGetSymbolAddress((void**)&c1, g_c1);
    cudaGetSymbolAddress((void**)&c2, g_c2);
    cudaGetSymbolAddress((void**)&c3, g_c3);
    cudaGetSymbolAddress((void**)&c4, g_c4);

    cudaFuncSetAttribute(gemm_fused<512, 0>,  cudaFuncAttributeMaxDynamicSharedMemorySize, SMEM_BYTES);
    cudaFuncSetAttribute(gemm_fused<1024, 0>, cudaFuncAttributeMaxDynamicSharedMemorySize, SMEM_BYTES);
    cudaFuncSetAttribute(gemm_fused<2048, 0>, cudaFuncAttributeMaxDynamicSharedMemorySize, SMEM_BYTES);
    cudaFuncSetAttribute(gemm_fused<1024, 1>, cudaFuncAttributeMaxDynamicSharedMemorySize, SMEM_BYTES);

    const int T = 256;
    split_x_kernel<<<(N_B * IN_F / 4 + T - 1) / T, T>>>(x, xs);
    prep_w1_split<<<(3 * H1D * IN_F / 2 + T - 1) / T, T>>>(W1, G1, B1, M1, V1, w1p, c1);
    prep_we_split<<<(H2D * H1D / 2 + T - 1) / T, T>>>(W2, G2, B2, M2, V2, w2p, c2, H2D, H1D);
    prep_we_split<<<(H1D * H2D / 2 + T - 1) / T, T>>>(W3, G3, B3, M3, V3, w3p, c3, H1D, H2D);
    prep_we_split<<<(IN_F * H1D / 2 + T - 1) / T, T>>>(W4, G4, B4, M4, V4, w4p, c4, IN_F, H1D);

    // L1: [8192,512] x [3072,512]^T -> h1 [8192,3072]
    gemm_fused<512, 0><<<dim3(3 * H1D / 128, N_B / 128), T, SMEM_BYTES>>>(xs, w1p, c1, h1, N_B, 3 * H1D);
    gate1_split<<<(N_B * 64 + T - 1) / T, T>>>(h1, h1s);
    // L2: [24576,1024] x [2048,1024]^T
    gemm_fused<1024, 0><<<dim3(H2D / 128, 3 * N_B / 128), T, SMEM_BYTES>>>(h1s, w2p, c2, h2, 3 * N_B, H2D);
    gate_split<<<(int)((N_B * (size_t)H2D / 16 + T - 1) / T), T>>>(h2, h2s, (size_t)N_B * H2D);
    // L3: [24576,2048] x [1024,2048]^T
    gemm_fused<2048, 0><<<dim3(H1D / 128, 3 * N_B / 128), T, SMEM_BYTES>>>(h2s, w3p, c3, h3, 3 * N_B, H1D);
    gate_split<<<(int)((N_B * (size_t)H1D / 16 + T - 1) / T), T>>>(h3, h3s, (size_t)N_B * H1D);
    // L4: [24576,1024] x [512,1024]^T -> interleaved out [b][o][s]
    gemm_fused<1024, 1><<<dim3(IN_F / 128, 3 * N_B / 128), T, SMEM_BYTES>>>(h3s, w4p, c4, out, 3 * N_B, IN_F);
}

// round 14
// speedup vs baseline: 1.4069x; 1.0346x over previous
#include <cuda_runtime.h>
#include <cuda_fp16.h>
#include <cstdint>
#include <cstddef>

#define EPSBN 1e-5f
#define N_B   8192
#define IN_F  512
#define H1D   1024
#define H2D   2048

// -------------------- scratch -----------------------------------------------
__device__ __align__(16) __half g_xs [2ULL * N_B * IN_F];
__device__ __align__(16) float  g_h1 [(size_t)N_B * 3 * H1D];
__device__ __align__(16) __half g_h1s[2ULL * 3 * N_B * H1D];
__device__ __align__(16) float  g_h2 [(size_t)3 * N_B * H2D];
__device__ __align__(16) __half g_h2s[2ULL * 3 * N_B * H2D];
__device__ __align__(16) float  g_h3 [(size_t)3 * N_B * H1D];
__device__ __align__(16) __half g_h3s[2ULL * 3 * N_B * H1D];
__device__ __align__(16) __half g_w1p[2ULL * 3 * H1D * IN_F];
__device__ __align__(16) __half g_w2p[2ULL * H2D * H1D];
__device__ __align__(16) __half g_w3p[2ULL * H1D * H2D];
__device__ __align__(16) __half g_w4p[2ULL * IN_F * H1D];
__device__ float g_c1[3 * H1D];
__device__ float g_c2[H2D];
__device__ float g_c3[H1D];
__device__ float g_c4[IN_F];

// -------------------- helpers ------------------------------------------------
__device__ __forceinline__ uint32_t smem_u32(const void* p) {
    uint32_t a;
    asm("{ .reg .u64 t; cvta.to.shared.u64 t, %1; cvt.u32.u64 %0, t; }" : "=r"(a) : "l"(p));
    return a;
}
__device__ __forceinline__ uint32_t h2u(__half2 h) { return *(uint32_t*)&h; }
__device__ __forceinline__ void split2x2(float x0, float x1, uint32_t& hi, uint32_t& lo) {
    __half2 h = __floats2half2_rn(x0, x1);
    float2 f = __half22float2(h);
    __half2 l = __floats2half2_rn(x0 - f.x, x1 - f.y);
    hi = h2u(h); lo = h2u(l);
}
__device__ __forceinline__ float bn_scale(float g, float v) {
    float vv = v + EPSBN;
    float a = rsqrtf(vv);
    return g * (a * (1.5f - 0.5f * vv * a * a));
}
__device__ __forceinline__ void lds_x4(uint32_t* r, uint32_t addr) {
    asm volatile("ldmatrix.sync.aligned.m8n8.x4.shared.b16 {%0,%1,%2,%3}, [%4];"
                 : "=r"(r[0]), "=r"(r[1]), "=r"(r[2]), "=r"(r[3]) : "r"(addr));
}
__device__ __forceinline__ void mma16816(float* c, const uint32_t* a, const uint32_t* b) {
    asm volatile(
        "mma.sync.aligned.m16n8k16.row.col.f32.f16.f16.f32 "
        "{%0,%1,%2,%3}, {%4,%5,%6,%7}, {%8,%9}, {%0,%1,%2,%3};"
        : "+f"(c[0]), "+f"(c[1]), "+f"(c[2]), "+f"(c[3])
        : "r"(a[0]), "r"(a[1]), "r"(a[2]), "r"(a[3]), "r"(b[0]), "r"(b[1]));
}
__device__ __forceinline__ void mma16816_z(float* c, const uint32_t* a, const uint32_t* b) {
    asm volatile(
        "mma.sync.aligned.m16n8k16.row.col.f32.f16.f16.f32 "
        "{%0,%1,%2,%3}, {%4,%5,%6,%7}, {%8,%9}, {%10,%10,%10,%10};"
        : "=f"(c[0]), "=f"(c[1]), "=f"(c[2]), "=f"(c[3])
        : "r"(a[0]), "r"(a[1]), "r"(a[2]), "r"(a[3]), "r"(b[0]), "r"(b[1]), "f"(0.f));
}

// -------------------- weight prep (vectorized by 4 along K) ------------------
__global__ void prep_w1_split(const float* __restrict__ W, const float* __restrict__ g,
                              const float* __restrict__ be, const float* __restrict__ m,
                              const float* __restrict__ v, __half* __restrict__ Wp,
                              float* __restrict__ bias) {
    int t = blockIdx.x * blockDim.x + threadIdx.x;
    if (t >= 3 * H1D * IN_F / 4) return;
    int i = 4 * t;
    int row = i >> 9;
    float a = bn_scale(g[row], v[row]);
    float4 w = *(const float4*)&W[i];
    const size_t S = (size_t)3 * H1D * IN_F;
    uint2 hi, lo;
    split2x2(w.x * a, w.y * a, hi.x, lo.x);
    split2x2(w.z * a, w.w * a, hi.y, lo.y);
    *(uint2*)&Wp[i] = hi;
    *(uint2*)&Wp[i + S] = lo;
    if ((i & (IN_F - 1)) == 0) bias[row] = be[row] - m[row] * a;
}

__global__ void prep_we_split(const float* __restrict__ W, const float* __restrict__ g,
                              const float* __restrict__ be, const float* __restrict__ m,
                              const float* __restrict__ v, __half* __restrict__ Wp,
                              float* __restrict__ bias, int Cout, int K) {
    int t = blockIdx.x * blockDim.x + threadIdx.x;
    if (t >= Cout * K / 4) return;
    int i = 4 * t;
    int o = i / K;
    int k = i - o * K;
    float ax = 0.f, ay = 0.f, az = 0.f, aw = 0.f;
#pragma unroll
    for (int s = 0; s < 3; s++) {
        float a = bn_scale(g[s * Cout + o], v[s * Cout + o]);
        float4 w = *(const float4*)&W[(size_t)(s * Cout + o) * K + k];
        ax += a * w.x;
        ay += a * w.y;
        az += a * w.z;
        aw += a * w.w;
    }
    const size_t S = (size_t)Cout * K;
    uint2 hi, lo;
    split2x2(ax, ay, hi.x, lo.x);
    split2x2(az, aw, hi.y, lo.y);
    *(uint2*)&Wp[i] = hi;
    *(uint2*)&Wp[i + S] = lo;
    if (k == 0) {
        float cb = 0.f;
#pragma unroll
        for (int s = 0; s < 3; s++) {
            float a = bn_scale(g[s * Cout + o], v[s * Cout + o]);
            cb += be[s * Cout + o] - m[s * Cout + o] * a;
        }
        bias[o] = cb;
    }
}

// -------------------- activation split / gate (R10 config: 8 elems/plane) ----
__global__ void split_x_kernel(const float* __restrict__ x, __half* __restrict__ o) {
    int i = blockIdx.x * blockDim.x + threadIdx.x;
    if (i >= N_B * IN_F / 4) return;
    float4 v = ((const float4*)x)[i];
    const size_t S = (size_t)N_B * IN_F;
    uint2 hi, lo;
    split2x2(v.x, v.y, hi.x, lo.x);
    split2x2(v.z, v.w, hi.y, lo.y);
    ((uint2*)o)[i] = hi;
    ((uint2*)(o + S))[i] = lo;
}

// h1 fp32 [b][s*1024+o] -> gated+split [lvl][s][b][o]; 8 elems/plane/thread
__global__ void gate1_split(const float* __restrict__ h1, __half* __restrict__ out) {
    int i = blockIdx.x * blockDim.x + threadIdx.x;
    if (i >= N_B * 128) return;
    int b = i >> 7;
    int o8 = i & 127;
    const float4* row = (const float4*)(h1 + (size_t)b * 3072);
    float4 va[3], vb[3];
#pragma unroll
    for (int s = 0; s < 3; s++) {
        va[s] = row[s * 256 + o8 * 2];
        vb[s] = row[s * 256 + o8 * 2 + 1];
    }
    float4 ma, mb;
    ma.x = (va[0].x + va[1].x + va[2].x > 0.f) ? 1.f : 0.f;
    ma.y = (va[0].y + va[1].y + va[2].y > 0.f) ? 1.f : 0.f;
    ma.z = (va[0].z + va[1].z + va[2].z > 0.f) ? 1.f : 0.f;
    ma.w = (va[0].w + va[1].w + va[2].w > 0.f) ? 1.f : 0.f;
    mb.x = (vb[0].x + vb[1].x + vb[2].x > 0.f) ? 1.f : 0.f;
    mb.y = (vb[0].y + vb[1].y + vb[2].y > 0.f) ? 1.f : 0.f;
    mb.z = (vb[0].z + vb[1].z + vb[2].z > 0.f) ? 1.f : 0.f;
    mb.w = (vb[0].w + vb[1].w + vb[2].w > 0.f) ? 1.f : 0.f;
    const size_t PL = (size_t)3 * N_B * H1D;
#pragma unroll
    for (int s = 0; s < 3; s++) {
        uint4 hi, lo;
        split2x2(va[s].x * ma.x, va[s].y * ma.y, hi.x, lo.x);
        split2x2(va[s].z * ma.z, va[s].w * ma.w, hi.y, lo.y);
        split2x2(vb[s].x * mb.x, vb[s].y * mb.y, hi.z, lo.z);
        split2x2(vb[s].z * mb.z, vb[s].w * mb.w, hi.w, lo.w);
        size_t base = (size_t)s * N_B * H1D + (size_t)b * H1D + (o8 << 3);
        *(uint4*)(out + base) = hi;
        *(uint4*)(out + PL + base) = lo;
    }
}

// h fp32 plane-major [s][plane] -> gated+split [lvl][s][plane]; 8 elems/plane/thread
__global__ void gate_split(const float* __restrict__ h, __half* __restrict__ out,
                           size_t plane) {
    size_t i = (size_t)blockIdx.x * blockDim.x + threadIdx.x;
    size_t q8 = plane >> 3;
    if (i >= q8) return;
    const float4* h4 = (const float4*)h;
    size_t p4 = plane >> 2;
    size_t i2 = i * 2;
    float4 va[3], vb[3];
#pragma unroll
    for (int s = 0; s < 3; s++) {
        va[s] = h4[i2 + (size_t)s * p4];
        vb[s] = h4[i2 + 1 + (size_t)s * p4];
    }
    float4 ma, mb;
    ma.x = (va[0].x + va[1].x + va[2].x > 0.f) ? 1.f : 0.f;
    ma.y = (va[0].y + va[1].y + va[2].y > 0.f) ? 1.f : 0.f;
    ma.z = (va[0].z + va[1].z + va[2].z > 0.f) ? 1.f : 0.f;
    ma.w = (va[0].w + va[1].w + va[2].w > 0.f) ? 1.f : 0.f;
    mb.x = (vb[0].x + vb[1].x + vb[2].x > 0.f) ? 1.f : 0.f;
    mb.y = (vb[0].y + vb[1].y + vb[2].y > 0.f) ? 1.f : 0.f;
    mb.z = (vb[0].z + vb[1].z + vb[2].z > 0.f) ? 1.f : 0.f;
    mb.w = (vb[0].w + vb[1].w + vb[2].w > 0.f) ? 1.f : 0.f;
    const size_t PL = 3 * plane;
#pragma unroll
    for (int s = 0; s < 3; s++) {
        uint4 hi, lo;
        split2x2(va[s].x * ma.x, va[s].y * ma.y, hi.x, lo.x);
        split2x2(va[s].z * ma.z, va[s].w * ma.w, hi.y, lo.y);
        split2x2(vb[s].x * mb.x, vb[s].y * mb.y, hi.z, lo.z);
        split2x2(vb[s].z * mb.z, vb[s].w * mb.w, hi.w, lo.w);
        size_t base = (size_t)s * plane + (i << 3);
        *(uint4*)(out + base) = hi;
        *(uint4*)(out + PL + base) = lo;
    }
}

// -------------------- fused 3-product fp16 HMMA GEMM (R10 config) ------------
// C = hh + hl + lh + bias. 128x128 tile, triple-buffered 64KB super-stages
// (192KB smem), cp.async 2 ahead, wait_group 1. tacc chain = 12 mma,
// RN drain per stage.
#define TSZ 16384
#define SUPER (4 * TSZ)
#define NBUF 3
#define SMEM_BYTES (NBUF * SUPER)

__device__ __forceinline__ void load_tile16(uint32_t dst, const __half* src,
                                            int row0, int KD, int k0, int tid) {
#pragma unroll
    for (int j = 0; j < 4; j++) {
        int id = j * 256 + tid;
        int row = id >> 3, c = id & 7;
        uint32_t d = dst + (row << 7) + (((c ^ row) & 7) << 4);
        const void* s = (const char*)(src + (size_t)(row0 + row) * KD + k0) + (c << 4);
        asm volatile("cp.async.cg.shared.global [%0], [%1], 16;" :: "r"(d), "l"(s));
    }
}

__device__ __forceinline__ void load_super(uint32_t buf, const __half* A0,
                                           const __half* B0, size_t pas, size_t pbs,
                                           int m0, int n0, int KD, int k0, int tid) {
#pragma unroll
    for (int lvl = 0; lvl < 2; lvl++) {
        load_tile16(buf + lvl * TSZ, A0 + (size_t)lvl * pas, m0, KD, k0, tid);
        load_tile16(buf + (2 + lvl) * TSZ, B0 + (size_t)lvl * pbs, n0, KD, k0, tid);
    }
    asm volatile("cp.async.commit_group;" ::: "memory");
}

template <int KDIM, int ILV>
__global__ void __launch_bounds__(256, 1)
gemm_fused(const __half* __restrict__ A0, const __half* __restrict__ B0,
           const float* __restrict__ bias, float* __restrict__ C, int M, int N) {
    extern __shared__ __align__(1024) char dsm[];
    const uint32_t Sb = smem_u32(dsm);

    const int tid = threadIdx.x;
    const int wid = tid >> 5;
    const int lane = tid & 31;
    const int warp_m = wid & 1;
    const int warp_n = wid >> 1;
    const int m0 = blockIdx.y * 128;
    const int n0 = blockIdx.x * 128;

    uint32_t aoff[4], boff[2];
#pragma unroll
    for (int mt = 0; mt < 4; mt++)
        aoff[mt] = (uint32_t)(warp_m * 64 + mt * 16 + (lane & 15)) << 7;
#pragma unroll
    for (int np = 0; np < 2; np++)
        boff[np] = (uint32_t)(warp_n * 32 + np * 16 + ((lane >> 4) << 3) + (lane & 7)) << 7;
    const int l7 = lane & 7;
    const int cha = lane >> 4;
    const int chb = (lane >> 3) & 1;

    float acc[4][4][4];
#pragma unroll
    for (int i = 0; i < 4; i++)
#pragma unroll
        for (int j = 0; j < 4; j++)
#pragma unroll
            for (int q = 0; q < 4; q++) acc[i][j][q] = 0.f;

    constexpr int NSUP = KDIM / 64;
    const size_t pas = (size_t)M * KDIM, pbs = (size_t)N * KDIM;

    load_super(Sb + 0 * SUPER, A0, B0, pas, pbs, m0, n0, KDIM, 0, tid);
    load_super(Sb + 1 * SUPER, A0, B0, pas, pbs, m0, n0, KDIM, 64, tid);

    int buf_c = 0;
    for (int t = 0; t < NSUP; t++) {
        if (t + 1 < NSUP) {
            asm volatile("cp.async.wait_group 1;" ::: "memory");
        } else {
            asm volatile("cp.async.wait_group 0;" ::: "memory");
        }
        __syncthreads();

        if (t + 2 < NSUP) {
            int buf_n = buf_c + 2;
            if (buf_n >= NBUF) buf_n -= NBUF;
            load_super(Sb + buf_n * SUPER, A0, B0, pas, pbs, m0, n0, KDIM,
                       (t + 2) * 64, tid);
        }

        const uint32_t Ab = Sb + buf_c * SUPER;
        const uint32_t Bb = Ab + 2 * TSZ;

        float tacc[4][4][4];
#pragma unroll
        for (int kk = 0; kk < 4; kk++) {
            const uint32_t swa = (uint32_t)(((2 * kk + cha) ^ l7) & 7) << 4;
            const uint32_t swb = (uint32_t)(((2 * kk + chb) ^ l7) & 7) << 4;

            uint32_t b[2][2][4];
#pragma unroll
            for (int lvl = 0; lvl < 2; lvl++)
#pragma unroll
                for (int np = 0; np < 2; np++)
                    lds_x4(b[lvl][np], Bb + lvl * TSZ + boff[np] + swb);

            uint32_t a[4][4];
#pragma unroll
            for (int mt = 0; mt < 4; mt++) lds_x4(a[mt], Ab + 0 * TSZ + aoff[mt] + swa);
            if (kk == 0) {
#pragma unroll
                for (int mt = 0; mt < 4; mt++)
#pragma unroll
                    for (int nt = 0; nt < 4; nt++)
                        mma16816_z(tacc[mt][nt], a[mt], &b[0][nt >> 1][(nt & 1) * 2]);
            } else {
#pragma unroll
                for (int mt = 0; mt < 4; mt++)
#pragma unroll
                    for (int nt = 0; nt < 4; nt++)
                        mma16816(tacc[mt][nt], a[mt], &b[0][nt >> 1][(nt & 1) * 2]);
            }
#pragma unroll
            for (int mt = 0; mt < 4; mt++)
#pragma unroll
                for (int nt = 0; nt < 4; nt++)
                    mma16816(tacc[mt][nt], a[mt], &b[1][nt >> 1][(nt & 1) * 2]);
#pragma unroll
            for (int mt = 0; mt < 4; mt++) lds_x4(a[mt], Ab + 1 * TSZ + aoff[mt] + swa);
#pragma unroll
            for (int mt = 0; mt < 4; mt++)
#pragma unroll
                for (int nt = 0; nt < 4; nt++)
                    mma16816(tacc[mt][nt], a[mt], &b[0][nt >> 1][(nt & 1) * 2]);
        }
#pragma unroll
        for (int i = 0; i < 4; i++)
#pragma unroll
            for (int j = 0; j < 4; j++)
#pragma unroll
                for (int q = 0; q < 4; q++) acc[i][j][q] += tacc[i][j][q];

        buf_c++;
        if (buf_c >= NBUF) buf_c -= NBUF;
    }

    // -------------------- epilogue --------------------
#pragma unroll
    for (int mt = 0; mt < 4; mt++) {
#pragma unroll
        for (int nt = 0; nt < 4; nt++) {
            int r0 = m0 + warp_m * 64 + mt * 16 + (lane >> 2);
            int cc = n0 + warp_n * 32 + nt * 8 + (lane & 3) * 2;
            float b0 = bias[cc], b1 = bias[cc + 1];
            float* ac = acc[mt][nt];
            if (!ILV) {
                float2 v0 = make_float2(ac[0] + b0, ac[1] + b1);
                float2 v1 = make_float2(ac[2] + b0, ac[3] + b1);
                *(float2*)(C + (size_t)r0 * N + cc) = v0;
                *(float2*)(C + (size_t)(r0 + 8) * N + cc) = v1;
            } else {
                int s0 = r0 >> 13, bb0 = r0 & 8191;
                int r1 = r0 + 8;
                int s1 = r1 >> 13, bb1 = r1 & 8191;
                C[(size_t)bb0 * (N * 3) + (size_t)cc * 3 + s0] = ac[0] + b0;
                C[(size_t)bb0 * (N * 3) + (size_t)(cc + 1) * 3 + s0] = ac[1] + b1;
                C[(size_t)bb1 * (N * 3) + (size_t)cc * 3 + s1] = ac[2] + b0;
                C[(size_t)bb1 * (N * 3) + (size_t)(cc + 1) * 3 + s1] = ac[3] + b1;
            }
        }
    }
}

// -------------------- launch --------------------------------------------------
extern "C" void kernel_launch(void* const* d_in, const int* in_sizes, int n_in,
                              void* d_out, int out_size) {
    const float* x  = (const float*)d_in[0];
    const float *W1 = (const float*)d_in[1],  *G1 = (const float*)d_in[2],
                *B1 = (const float*)d_in[3],  *M1 = (const float*)d_in[4],
                *V1 = (const float*)d_in[5];
    const float *W2 = (const float*)d_in[6],  *G2 = (const float*)d_in[7],
                *B2 = (const float*)d_in[8],  *M2 = (const float*)d_in[9],
                *V2 = (const float*)d_in[10];
    const float *W3 = (const float*)d_in[11], *G3 = (const float*)d_in[12],
                *B3 = (const float*)d_in[13], *M3 = (const float*)d_in[14],
                *V3 = (const float*)d_in[15];
    const float *W4 = (const float*)d_in[16], *G4 = (const float*)d_in[17],
                *B4 = (const float*)d_in[18], *M4 = (const float*)d_in[19],
                *V4 = (const float*)d_in[20];
    float* out = (float*)d_out;

    __half *xs, *h1s, *h2s, *h3s, *w1p, *w2p, *w3p, *w4p;
    float *h1, *h2, *h3, *c1, *c2, *c3, *c4;
    cudaGetSymbolAddress((void**)&xs, g_xs);
    cudaGetSymbolAddress((void**)&h1, g_h1);
    cudaGetSymbolAddress((void**)&h1s, g_h1s);
    cudaGetSymbolAddress((void**)&h2, g_h2);
    cudaGetSymbolAddress((void**)&h2s, g_h2s);
    cudaGetSymbolAddress((void**)&h3, g_h3);
    cudaGetSymbolAddress((void**)&h3s, g_h3s);
    cudaGetSymbolAddress((void**)&w1p, g_w1p);
    cudaGetSymbolAddress((void**)&w2p, g_w2p);
    cudaGetSymbolAddress((void**)&w3p, g_w3p);
    cudaGetSymbolAddress((void**)&w4p, g_w4p);
    cudaGetSymbolAddress((void**)&c1, g_c1);
    cudaGetSymbolAddress((void**)&c2, g_c2);
    cudaGetSymbolAddress((void**)&c3, g_c3);
    cudaGetSymbolAddress((void**)&c4, g_c4);

    cudaFuncSetAttribute(gemm_fused<512, 0>,  cudaFuncAttributeMaxDynamicSharedMemorySize, SMEM_BYTES);
    cudaFuncSetAttribute(gemm_fused<1024, 0>, cudaFuncAttributeMaxDynamicSharedMemorySize, SMEM_BYTES);
    cudaFuncSetAttribute(gemm_fused<2048, 0>, cudaFuncAttributeMaxDynamicSharedMemorySize, SMEM_BYTES);
    cudaFuncSetAttribute(gemm_fused<1024, 1>, cudaFuncAttributeMaxDynamicSharedMemorySize, SMEM_BYTES);

    const int T = 256;
    split_x_kernel<<<(N_B * IN_F / 4 + T - 1) / T, T>>>(x, xs);
    prep_w1_split<<<(3 * H1D * IN_F / 4 + T - 1) / T, T>>>(W1, G1, B1, M1, V1, w1p, c1);
    prep_we_split<<<(H2D * H1D / 4 + T - 1) / T, T>>>(W2, G2, B2, M2, V2, w2p, c2, H2D, H1D);
    prep_we_split<<<(H1D * H2D / 4 + T - 1) / T, T>>>(W3, G3, B3, M3, V3, w3p, c3, H1D, H2D);
    prep_we_split<<<(IN_F * H1D / 4 + T - 1) / T, T>>>(W4, G4, B4, M4, V4, w4p, c4, IN_F, H1D);

    // L1: [8192,512] x [3072,512]^T -> h1 [8192,3072]
    gemm_fused<512, 0><<<dim3(3 * H1D / 128, N_B / 128), T, SMEM_BYTES>>>(xs, w1p, c1, h1, N_B, 3 * H1D);
    gate1_split<<<(N_B * 128 + T - 1) / T, T>>>(h1, h1s);
    // L2: [24576,1024] x [2048,1024]^T
    gemm_fused<1024, 0><<<dim3(H2D / 128, 3 * N_B / 128), T, SMEM_BYTES>>>(h1s, w2p, c2, h2, 3 * N_B, H2D);
    gate_split<<<(int)((N_B * (size_t)H2D / 8 + T - 1) / T), T>>>(h2, h2s, (size_t)N_B * H2D);
    // L3: [24576,2048] x [1024,2048]^T
    gemm_fused<2048, 0><<<dim3(H1D / 128, 3 * N_B / 128), T, SMEM_BYTES>>>(h2s, w3p, c3, h3, 3 * N_B, H1D);
    gate_split<<<(int)((N_B * (size_t)H1D / 8 + T - 1) / T), T>>>(h3, h3s, (size_t)N_B * H1D);
    // L4: [24576,1024] x [512,1024]^T -> interleaved out [b][o][s]
    gemm_fused<1024, 1><<<dim3(IN_F / 128, 3 * N_B / 128), T, SMEM_BYTES>>>(h3s, w4p, c4, out, 3 * N_B, IN_F);
}